// round 2
// baseline (speedup 1.0000x reference)
#include <cuda_runtime.h>
#include <cstdint>

// Problem constants (fixed by the dataset generator)
#define MAXN 100000
#define MAXE 800000
#define H 64

// ---------------- device scratch (no allocation allowed) ----------------
__device__ float g_xenc[MAXN * H];     // relu(x@Wn+bn)
__device__ float g_h[MAXN * H];        // conv pre-aggregation h = X@Wc
__device__ float g_acc[MAXN * H];      // conv scatter accumulator
__device__ float g_x1[MAXN * H];
__device__ float g_x2[MAXN * H];
__device__ float g_res[MAXN * H];      // x_enc@Wr + br
__device__ float g_tw[1000 * H];       // relu(Temb@Wt+bt) table
__device__ float g_dinv[MAXN];         // deg accumulation then rsqrt(deg+1)
__device__ int   g_outdeg[MAXN];
__device__ float g_fus[MAXN * 3 * H];  // fusion blocks 1..3 accumulators
__device__ float g_nf[MAXN * 4 * H];   // node_fusion [N,256]
__device__ float g_hid[MAXN * H];      // MLP hidden

// ---------------- degree kernels ----------------
__global__ void k_deg(const int* __restrict__ src, const int* __restrict__ dst,
                      float* __restrict__ degf, int* __restrict__ outdeg, int E) {
    int i = blockIdx.x * blockDim.x + threadIdx.x;
    if (i < E) {
        atomicAdd(&degf[dst[i]], 1.0f);
        atomicAdd(&outdeg[src[i]], 1);
    }
}

__global__ void k_dinv(float* __restrict__ degf, int N) {
    int i = blockIdx.x * blockDim.x + threadIdx.x;
    if (i < N) degf[i] = rsqrtf(degf[i] + 1.0f);  // +1 self loop; always > 0
}

// ---------------- time table: relu(Temb@Wt + bt) ----------------
__global__ void k_ttable(const float* __restrict__ Temb, const float* __restrict__ Wt,
                         const float* __restrict__ bt, float* __restrict__ tw) {
    __shared__ float er[H];
    int t = blockIdx.x;
    int c = threadIdx.x;
    er[c] = Temb[t * H + c];
    __syncthreads();
    float a = bt[c];
#pragma unroll
    for (int k = 0; k < H; k++) a += er[k] * Wt[k * H + c];
    tw[t * H + c] = fmaxf(a, 0.0f);
}

// ---------------- generic [M,K] @ [K,64] tiled GEMM ----------------
template <int K, bool RELU>
__global__ void k_gemm64(const float* __restrict__ A, const float* __restrict__ W,
                         const float* __restrict__ bias, float* __restrict__ C, int M) {
    __shared__ float As[16][64];
    __shared__ float Ws[16][64];
    const int m0 = blockIdx.x * 64;
    const int tid = threadIdx.x;
    const int col = tid & 63;
    const int rg = tid >> 6;  // 0..3

    float acc[16];
#pragma unroll
    for (int i = 0; i < 16; i++) acc[i] = 0.0f;

    for (int kc = 0; kc < K; kc += 16) {
        __syncthreads();
#pragma unroll
        for (int i = tid; i < 1024; i += 256) {
            int kk = i & 15, r = i >> 4;
            int row = m0 + r;
            As[kk][r] = (row < M) ? A[(size_t)row * K + kc + kk] : 0.0f;
        }
#pragma unroll
        for (int i = tid; i < 1024; i += 256) {
            int c = i & 63, kk = i >> 6;
            Ws[kk][c] = W[(size_t)(kc + kk) * 64 + c];
        }
        __syncthreads();
#pragma unroll
        for (int kk = 0; kk < 16; kk++) {
            float w = Ws[kk][col];
#pragma unroll
            for (int rr = 0; rr < 16; rr++)
                acc[rr] += As[kk][rg + 4 * rr] * w;
        }
    }
    float b = bias ? bias[col] : 0.0f;
#pragma unroll
    for (int rr = 0; rr < 16; rr++) {
        int row = m0 + rg + 4 * rr;
        if (row < M) {
            float v = acc[rr] + b;
            if (RELU) v = fmaxf(v, 0.0f);
            C[(size_t)row * 64 + col] = v;
        }
    }
}

// ---------------- GCN message scatter: acc[dst] += h[src] * dinv[s]*dinv[d] ----------------
__global__ void k_conv_scatter(const float* __restrict__ h, const int* __restrict__ src,
                               const int* __restrict__ dst, const float* __restrict__ dinv,
                               float* __restrict__ acc, int E) {
    int u = blockIdx.x * blockDim.x + threadIdx.x;
    int total = E * 16;
    if (u >= total) return;
    int e = u >> 4, q = u & 15;
    int s = src[e], d = dst[e];
    float nrm = dinv[s] * dinv[d];
    float4 v = ((const float4*)(h + (size_t)s * 64))[q];
    v.x *= nrm; v.y *= nrm; v.z *= nrm; v.w *= nrm;
    atomicAdd(((float4*)(acc + (size_t)d * 64)) + q, v);
}

// ---------------- conv finalize: out = relu(acc + h/deg + bias [+ res]) ----------------
__global__ void k_conv_fin(const float* __restrict__ acc, const float* __restrict__ h,
                           const float* __restrict__ dinv, const float* __restrict__ bias,
                           const float* __restrict__ res, float* __restrict__ out, int N) {
    int i = blockIdx.x * blockDim.x + threadIdx.x;
    if (i >= N * 64) return;
    int n = i >> 6, c = i & 63;
    float di = dinv[n];
    float v = acc[i] + h[i] * di * di + bias[c];
    if (res) v += res[i];
    out[i] = fmaxf(v, 0.0f);
}

// ---------------- fusion scatter: per edge, warp-per-edge ----------------
// fus[src] += [ x2[dst] | relu(edge_attr@We+be) | tw[ts] ]   (3 blocks of 64)
__global__ void k_fusion_scatter(const float* __restrict__ x2, const float* __restrict__ tw,
                                 const float* __restrict__ edge_attr,
                                 const float* __restrict__ We, const float* __restrict__ be,
                                 const int* __restrict__ src, const int* __restrict__ dst,
                                 const int* __restrict__ ts, float* __restrict__ fus, int E) {
    __shared__ float Ws[32 * 64];
    __shared__ float bes[64];
    int tid = threadIdx.x;
    for (int i = tid; i < 32 * 64; i += blockDim.x) Ws[i] = We[i];
    if (tid < 64) bes[tid] = be[tid];
    __syncthreads();

    int warp = (blockIdx.x * blockDim.x + tid) >> 5;
    int lane = tid & 31;
    if (warp >= E) return;
    int e = warp;
    int s = src[e], d = dst[e];
    int t = min(max(ts[e], 0), 999);

    float2 xd = *(const float2*)(x2 + (size_t)d * 64 + 2 * lane);
    float2 te = *(const float2*)(tw + (size_t)t * 64 + 2 * lane);
    float ea = edge_attr[(size_t)e * 32 + lane];

    float a0 = 0.0f, a1 = 0.0f;
#pragma unroll
    for (int k = 0; k < 32; k++) {
        float v = __shfl_sync(0xffffffffu, ea, k);
        float2 w = *(const float2*)&Ws[k * 64 + 2 * lane];
        a0 += v * w.x;
        a1 += v * w.y;
    }
    float2 ee;
    ee.x = fmaxf(a0 + bes[2 * lane], 0.0f);
    ee.y = fmaxf(a1 + bes[2 * lane + 1], 0.0f);

    float* base = fus + (size_t)s * 192;
    atomicAdd((float2*)(base + 2 * lane), xd);
    atomicAdd((float2*)(base + 64 + 2 * lane), ee);
    atomicAdd((float2*)(base + 128 + 2 * lane), te);
}

// ---------------- fusion finalize: build node_fusion [N,256] with fallback ----------------
__global__ void k_fusion_fin(const float* __restrict__ x2, const float* __restrict__ xenc,
                             const float* __restrict__ fus, const int* __restrict__ outdeg,
                             float* __restrict__ nf, int N) {
    __shared__ float sm[2];
    int n = blockIdx.x;
    int c = threadIdx.x;  // 64
    int od = outdeg[n];
    float* o = nf + (size_t)n * 256;
    if (od == 0) {
        float v = xenc[(size_t)n * 64 + c];
        o[c] = v; o[64 + c] = v; o[128 + c] = v; o[192 + c] = v;
        return;
    }
    float inv = 1.0f / (float)od;
    float f0 = x2[(size_t)n * 64 + c];
    const float* fb = fus + (size_t)n * 192;
    float f1 = fb[c] * inv;
    float f2 = fb[64 + c] * inv;
    float f3 = fb[128 + c] * inv;
    float s = fabsf(f0) + fabsf(f1) + fabsf(f2) + fabsf(f3);
#pragma unroll
    for (int off = 16; off > 0; off >>= 1) s += __shfl_xor_sync(0xffffffffu, s, off);
    if ((c & 31) == 0) sm[c >> 5] = s;
    __syncthreads();
    float total = sm[0] + sm[1];
    if (total < 1e-6f) {
        float v = xenc[(size_t)n * 64 + c];
        o[c] = v; o[64 + c] = v; o[128 + c] = v; o[192 + c] = v;
    } else {
        o[c] = f0; o[64 + c] = f1; o[128 + c] = f2; o[192 + c] = f3;
    }
}

// ---------------- MLP output: out = hid @ Wm2 + bm2 (64->2) ----------------
__global__ void k_mlp_out(const float* __restrict__ hid, const float* __restrict__ Wm2,
                          const float* __restrict__ bm2, float* __restrict__ out, int N) {
    int warp = (blockIdx.x * blockDim.x + threadIdx.x) >> 5;
    int lane = threadIdx.x & 31;
    if (warp >= N) return;
    int n = warp;
    float h0 = hid[(size_t)n * 64 + lane];
    float h1 = hid[(size_t)n * 64 + 32 + lane];
    float o0 = h0 * Wm2[lane * 2] + h1 * Wm2[(32 + lane) * 2];
    float o1 = h0 * Wm2[lane * 2 + 1] + h1 * Wm2[(32 + lane) * 2 + 1];
#pragma unroll
    for (int off = 16; off > 0; off >>= 1) {
        o0 += __shfl_xor_sync(0xffffffffu, o0, off);
        o1 += __shfl_xor_sync(0xffffffffu, o1, off);
    }
    if (lane == 0) {
        out[(size_t)n * 2]     = o0 + bm2[0];
        out[(size_t)n * 2 + 1] = o1 + bm2[1];
    }
}

// ---------------- host launcher ----------------
extern "C" void kernel_launch(void* const* d_in, const int* in_sizes, int n_in,
                              void* d_out, int out_size) {
    const float* x    = (const float*)d_in[0];
    const int*   ei   = (const int*)d_in[1];
    const float* eatt = (const float*)d_in[2];
    const int*   ts   = (const int*)d_in[3];
    const float* Wn   = (const float*)d_in[4];
    const float* bn   = (const float*)d_in[5];
    const float* We   = (const float*)d_in[6];
    const float* be   = (const float*)d_in[7];
    const float* Temb = (const float*)d_in[8];
    const float* Wt   = (const float*)d_in[9];
    const float* bt   = (const float*)d_in[10];
    const float* Wc1  = (const float*)d_in[11];
    const float* bc1  = (const float*)d_in[12];
    const float* Wc2  = (const float*)d_in[13];
    const float* bc2  = (const float*)d_in[14];
    const float* Wr   = (const float*)d_in[15];
    const float* br   = (const float*)d_in[16];
    const float* Wm1  = (const float*)d_in[17];
    const float* bm1  = (const float*)d_in[18];
    const float* Wm2  = (const float*)d_in[19];
    const float* bm2  = (const float*)d_in[20];

    const int N = in_sizes[0] / 128;
    const int E = in_sizes[3];
    const int* src = ei;
    const int* dst = ei + E;

    float *p_xenc, *p_h, *p_acc, *p_x1, *p_x2, *p_res, *p_tw, *p_dinv, *p_fus, *p_nf, *p_hid;
    int* p_outdeg;
    cudaGetSymbolAddress((void**)&p_xenc, g_xenc);
    cudaGetSymbolAddress((void**)&p_h, g_h);
    cudaGetSymbolAddress((void**)&p_acc, g_acc);
    cudaGetSymbolAddress((void**)&p_x1, g_x1);
    cudaGetSymbolAddress((void**)&p_x2, g_x2);
    cudaGetSymbolAddress((void**)&p_res, g_res);
    cudaGetSymbolAddress((void**)&p_tw, g_tw);
    cudaGetSymbolAddress((void**)&p_dinv, g_dinv);
    cudaGetSymbolAddress((void**)&p_outdeg, g_outdeg);
    cudaGetSymbolAddress((void**)&p_fus, g_fus);
    cudaGetSymbolAddress((void**)&p_nf, g_nf);
    cudaGetSymbolAddress((void**)&p_hid, g_hid);

    float* outp = (float*)d_out;

    // zero accumulators
    cudaMemsetAsync(p_dinv, 0, (size_t)N * sizeof(float));
    cudaMemsetAsync(p_outdeg, 0, (size_t)N * sizeof(int));
    cudaMemsetAsync(p_acc, 0, (size_t)N * 64 * sizeof(float));
    cudaMemsetAsync(p_fus, 0, (size_t)N * 192 * sizeof(float));

    // degrees
    k_deg<<<(E + 255) / 256, 256>>>(src, dst, p_dinv, p_outdeg, E);
    k_dinv<<<(N + 255) / 256, 256>>>(p_dinv, N);

    // time table
    k_ttable<<<1000, 64>>>(Temb, Wt, bt, p_tw);

    // x_enc = relu(x @ Wn + bn)
    k_gemm64<128, true><<<(N + 63) / 64, 256>>>(x, Wn, bn, p_xenc, N);

    // conv1
    k_gemm64<64, false><<<(N + 63) / 64, 256>>>(p_xenc, Wc1, nullptr, p_h, N);
    k_conv_scatter<<<(E * 16 + 255) / 256, 256>>>(p_h, src, dst, p_dinv, p_acc, E);
    k_conv_fin<<<(N * 64 + 255) / 256, 256>>>(p_acc, p_h, p_dinv, bc1, nullptr, p_x1, N);

    // residual (x_enc @ Wr + br)
    k_gemm64<64, false><<<(N + 63) / 64, 256>>>(p_xenc, Wr, br, p_res, N);

    // conv2
    cudaMemsetAsync(p_acc, 0, (size_t)N * 64 * sizeof(float));
    k_gemm64<64, false><<<(N + 63) / 64, 256>>>(p_x1, Wc2, nullptr, p_h, N);
    k_conv_scatter<<<(E * 16 + 255) / 256, 256>>>(p_h, src, dst, p_dinv, p_acc, E);
    k_conv_fin<<<(N * 64 + 255) / 256, 256>>>(p_acc, p_h, p_dinv, bc2, p_res, p_x2, N);

    // fusion scatter (edge_enc computed on the fly; time via table gather)
    k_fusion_scatter<<<(E + 7) / 8, 256>>>(p_x2, p_tw, eatt, We, be, src, dst, ts, p_fus, E);

    // node_fusion build + empty-node fallback
    k_fusion_fin<<<N, 64>>>(p_x2, p_xenc, p_fus, p_outdeg, p_nf, N);

    // classifier
    k_gemm64<256, true><<<(N + 63) / 64, 256>>>(p_nf, Wm1, bm1, p_hid, N);
    k_mlp_out<<<(N + 7) / 8, 256>>>(p_hid, Wm2, bm2, outp, N);
}

// round 3
// speedup vs baseline: 1.2667x; 1.2667x over previous
#include <cuda_runtime.h>
#include <cstdint>

// Problem constants (fixed by the dataset generator)
#define MAXN 100000
#define MAXE 800000
#define H 64

// ---------------- device scratch (no allocation allowed) ----------------
__device__ float g_xenc[MAXN * H];     // relu(x@Wn+bn)
__device__ float g_h[MAXN * H];        // conv pre-aggregation h' = (X@Wc)*dinv[row]
__device__ float g_acc[MAXN * H];      // conv scatter accumulator
__device__ float g_x1[MAXN * H];
__device__ float g_x2[MAXN * H];
__device__ float g_res[MAXN * H];      // x_enc@Wr + br
__device__ float g_tw[1000 * H];       // relu(Temb@Wt+bt) table
__device__ float g_dinv[MAXN];         // deg accumulation then rsqrt(deg+1)
__device__ int   g_outdeg[MAXN];
__device__ float g_fus[MAXN * 3 * H];  // fusion blocks 1..3 accumulators
__device__ float g_nf[MAXN * 4 * H];   // node_fusion [N,256]
__device__ float g_hid[MAXN * H];      // MLP hidden

// ---------------- degree kernels ----------------
__global__ void k_deg(const int* __restrict__ src, const int* __restrict__ dst,
                      float* __restrict__ degf, int* __restrict__ outdeg, int E) {
    int i = blockIdx.x * blockDim.x + threadIdx.x;
    if (i < E) {
        atomicAdd(&degf[dst[i]], 1.0f);
        atomicAdd(&outdeg[src[i]], 1);
    }
}

__global__ void k_dinv(float* __restrict__ degf, int N) {
    int i = blockIdx.x * blockDim.x + threadIdx.x;
    if (i < N) degf[i] = rsqrtf(degf[i] + 1.0f);  // +1 self loop; always > 0
}

// ---------------- time table: relu(Temb@Wt + bt) ----------------
__global__ void k_ttable(const float* __restrict__ Temb, const float* __restrict__ Wt,
                         const float* __restrict__ bt, float* __restrict__ tw) {
    __shared__ float er[H];
    int t = blockIdx.x;
    int c = threadIdx.x;
    er[c] = Temb[t * H + c];
    __syncthreads();
    float a = bt[c];
#pragma unroll
    for (int k = 0; k < H; k++) a += er[k] * Wt[k * H + c];
    tw[t * H + c] = fmaxf(a, 0.0f);
}

// ---------------- row-per-thread [M,K] @ [K,64] GEMM ----------------
// Each thread computes one full output row: 64 accumulators in registers.
// W staged in smem (<=32KB chunks); inner loads are LDS.128 broadcasts.
// Optional per-row output scale (dinv fold for GCN) applied after bias+relu.
template <int K, bool RELU>
__global__ __launch_bounds__(256)
void k_gemm_rows(const float* __restrict__ A, const float* __restrict__ W,
                 const float* __restrict__ bias, const float* __restrict__ rowscale,
                 float* __restrict__ C, int M) {
    constexpr int KC = (K < 128) ? K : 128;
    __shared__ float Wsm[KC * 64];
    __shared__ float bsm[64];
    const int tid = threadIdx.x;
    if (tid < 64) bsm[tid] = bias ? bias[tid] : 0.0f;

    const int row = blockIdx.x * 256 + tid;
    const int r = (row < M) ? row : (M - 1);
    const float4* __restrict__ Arow = (const float4*)(A + (size_t)r * K);

    float acc[64];
#pragma unroll
    for (int i = 0; i < 64; i++) acc[i] = 0.0f;

    for (int kc = 0; kc < K; kc += KC) {
        __syncthreads();
        for (int i = tid; i < KC * 16; i += 256)
            ((float4*)Wsm)[i] = ((const float4*)W)[kc * 16 + i];
        __syncthreads();
#pragma unroll 2
        for (int k4 = 0; k4 < KC / 4; k4++) {
            float4 a = Arow[(kc >> 2) + k4];
#pragma unroll
            for (int j = 0; j < 4; j++) {
                float av = (j == 0) ? a.x : (j == 1) ? a.y : (j == 2) ? a.z : a.w;
                const float4* wr = (const float4*)(Wsm + (k4 * 4 + j) * 64);
#pragma unroll
                for (int c = 0; c < 16; c++) {
                    float4 w = wr[c];
                    acc[c * 4 + 0] = fmaf(av, w.x, acc[c * 4 + 0]);
                    acc[c * 4 + 1] = fmaf(av, w.y, acc[c * 4 + 1]);
                    acc[c * 4 + 2] = fmaf(av, w.z, acc[c * 4 + 2]);
                    acc[c * 4 + 3] = fmaf(av, w.w, acc[c * 4 + 3]);
                }
            }
        }
    }

    if (row < M) {
        float sc = rowscale ? rowscale[row] : 1.0f;
        float4* __restrict__ Crow = (float4*)(C + (size_t)row * 64);
#pragma unroll
        for (int c = 0; c < 16; c++) {
            float4 v;
            v.x = acc[c * 4 + 0] + bsm[c * 4 + 0];
            v.y = acc[c * 4 + 1] + bsm[c * 4 + 1];
            v.z = acc[c * 4 + 2] + bsm[c * 4 + 2];
            v.w = acc[c * 4 + 3] + bsm[c * 4 + 3];
            if (RELU) {
                v.x = fmaxf(v.x, 0.0f); v.y = fmaxf(v.y, 0.0f);
                v.z = fmaxf(v.z, 0.0f); v.w = fmaxf(v.w, 0.0f);
            }
            v.x *= sc; v.y *= sc; v.z *= sc; v.w *= sc;
            Crow[c] = v;
        }
    }
}

// ---------------- GCN message scatter: acc[dst] += h'[src]  (h' pre-scaled by dinv[src]) ----
__global__ void k_conv_scatter(const float* __restrict__ h, const int* __restrict__ src,
                               const int* __restrict__ dst, float* __restrict__ acc, int E) {
    int u = blockIdx.x * blockDim.x + threadIdx.x;
    int total = E * 16;
    if (u >= total) return;
    int e = u >> 4, q = u & 15;
    float4 v = ((const float4*)h)[(size_t)src[e] * 16 + q];
    atomicAdd(((float4*)acc) + (size_t)dst[e] * 16 + q, v);
}

// ---------------- conv finalize: out = relu((acc + h'[n]) * dinv[n] + bias [+ res]) --------
__global__ void k_conv_fin(const float* __restrict__ acc, const float* __restrict__ h,
                           const float* __restrict__ dinv, const float* __restrict__ bias,
                           const float* __restrict__ res, float* __restrict__ out, int N) {
    int i = blockIdx.x * blockDim.x + threadIdx.x;
    if (i >= N * 64) return;
    int n = i >> 6, c = i & 63;
    float v = (acc[i] + h[i]) * dinv[n] + bias[c];
    if (res) v += res[i];
    out[i] = fmaxf(v, 0.0f);
}

// ---------------- fusion scatter: per edge, warp-per-edge ----------------
// fus[src] += [ x2[dst] | relu(edge_attr@We+be) | tw[ts] ]   (3 blocks of 64)
__global__ void k_fusion_scatter(const float* __restrict__ x2, const float* __restrict__ tw,
                                 const float* __restrict__ edge_attr,
                                 const float* __restrict__ We, const float* __restrict__ be,
                                 const int* __restrict__ src, const int* __restrict__ dst,
                                 const int* __restrict__ ts, float* __restrict__ fus, int E) {
    __shared__ float Ws[32 * 64];
    __shared__ float bes[64];
    int tid = threadIdx.x;
    for (int i = tid; i < 32 * 64; i += blockDim.x) Ws[i] = We[i];
    if (tid < 64) bes[tid] = be[tid];
    __syncthreads();

    int warp = (blockIdx.x * blockDim.x + tid) >> 5;
    int lane = tid & 31;
    if (warp >= E) return;
    int e = warp;
    int s = src[e], d = dst[e];
    int t = min(max(ts[e], 0), 999);

    float2 xd = *(const float2*)(x2 + (size_t)d * 64 + 2 * lane);
    float2 te = *(const float2*)(tw + (size_t)t * 64 + 2 * lane);
    float ea = edge_attr[(size_t)e * 32 + lane];

    float a0 = 0.0f, a1 = 0.0f;
#pragma unroll
    for (int k = 0; k < 32; k++) {
        float v = __shfl_sync(0xffffffffu, ea, k);
        float2 w = *(const float2*)&Ws[k * 64 + 2 * lane];
        a0 += v * w.x;
        a1 += v * w.y;
    }
    float2 ee;
    ee.x = fmaxf(a0 + bes[2 * lane], 0.0f);
    ee.y = fmaxf(a1 + bes[2 * lane + 1], 0.0f);

    float* base = fus + (size_t)s * 192;
    atomicAdd((float2*)(base + 2 * lane), xd);
    atomicAdd((float2*)(base + 64 + 2 * lane), ee);
    atomicAdd((float2*)(base + 128 + 2 * lane), te);
}

// ---------------- fusion finalize: build node_fusion [N,256] with fallback ----------------
__global__ void k_fusion_fin(const float* __restrict__ x2, const float* __restrict__ xenc,
                             const float* __restrict__ fus, const int* __restrict__ outdeg,
                             float* __restrict__ nf, int N) {
    __shared__ float sm[2];
    int n = blockIdx.x;
    int c = threadIdx.x;  // 64
    int od = outdeg[n];
    float* o = nf + (size_t)n * 256;
    if (od == 0) {
        float v = xenc[(size_t)n * 64 + c];
        o[c] = v; o[64 + c] = v; o[128 + c] = v; o[192 + c] = v;
        return;
    }
    float inv = 1.0f / (float)od;
    float f0 = x2[(size_t)n * 64 + c];
    const float* fb = fus + (size_t)n * 192;
    float f1 = fb[c] * inv;
    float f2 = fb[64 + c] * inv;
    float f3 = fb[128 + c] * inv;
    float s = fabsf(f0) + fabsf(f1) + fabsf(f2) + fabsf(f3);
#pragma unroll
    for (int off = 16; off > 0; off >>= 1) s += __shfl_xor_sync(0xffffffffu, s, off);
    if ((c & 31) == 0) sm[c >> 5] = s;
    __syncthreads();
    float total = sm[0] + sm[1];
    if (total < 1e-6f) {
        float v = xenc[(size_t)n * 64 + c];
        o[c] = v; o[64 + c] = v; o[128 + c] = v; o[192 + c] = v;
    } else {
        o[c] = f0; o[64 + c] = f1; o[128 + c] = f2; o[192 + c] = f3;
    }
}

// ---------------- MLP output: out = hid @ Wm2 + bm2 (64->2) ----------------
__global__ void k_mlp_out(const float* __restrict__ hid, const float* __restrict__ Wm2,
                          const float* __restrict__ bm2, float* __restrict__ out, int N) {
    int warp = (blockIdx.x * blockDim.x + threadIdx.x) >> 5;
    int lane = threadIdx.x & 31;
    if (warp >= N) return;
    int n = warp;
    float h0 = hid[(size_t)n * 64 + lane];
    float h1 = hid[(size_t)n * 64 + 32 + lane];
    float o0 = h0 * Wm2[lane * 2] + h1 * Wm2[(32 + lane) * 2];
    float o1 = h0 * Wm2[lane * 2 + 1] + h1 * Wm2[(32 + lane) * 2 + 1];
#pragma unroll
    for (int off = 16; off > 0; off >>= 1) {
        o0 += __shfl_xor_sync(0xffffffffu, o0, off);
        o1 += __shfl_xor_sync(0xffffffffu, o1, off);
    }
    if (lane == 0) {
        out[(size_t)n * 2]     = o0 + bm2[0];
        out[(size_t)n * 2 + 1] = o1 + bm2[1];
    }
}

// ---------------- host launcher ----------------
extern "C" void kernel_launch(void* const* d_in, const int* in_sizes, int n_in,
                              void* d_out, int out_size) {
    const float* x    = (const float*)d_in[0];
    const int*   ei   = (const int*)d_in[1];
    const float* eatt = (const float*)d_in[2];
    const int*   ts   = (const int*)d_in[3];
    const float* Wn   = (const float*)d_in[4];
    const float* bn   = (const float*)d_in[5];
    const float* We   = (const float*)d_in[6];
    const float* be   = (const float*)d_in[7];
    const float* Temb = (const float*)d_in[8];
    const float* Wt   = (const float*)d_in[9];
    const float* bt   = (const float*)d_in[10];
    const float* Wc1  = (const float*)d_in[11];
    const float* bc1  = (const float*)d_in[12];
    const float* Wc2  = (const float*)d_in[13];
    const float* bc2  = (const float*)d_in[14];
    const float* Wr   = (const float*)d_in[15];
    const float* br   = (const float*)d_in[16];
    const float* Wm1  = (const float*)d_in[17];
    const float* bm1  = (const float*)d_in[18];
    const float* Wm2  = (const float*)d_in[19];
    const float* bm2  = (const float*)d_in[20];

    const int N = in_sizes[0] / 128;
    const int E = in_sizes[3];
    const int* src = ei;
    const int* dst = ei + E;

    float *p_xenc, *p_h, *p_acc, *p_x1, *p_x2, *p_res, *p_tw, *p_dinv, *p_fus, *p_nf, *p_hid;
    int* p_outdeg;
    cudaGetSymbolAddress((void**)&p_xenc, g_xenc);
    cudaGetSymbolAddress((void**)&p_h, g_h);
    cudaGetSymbolAddress((void**)&p_acc, g_acc);
    cudaGetSymbolAddress((void**)&p_x1, g_x1);
    cudaGetSymbolAddress((void**)&p_x2, g_x2);
    cudaGetSymbolAddress((void**)&p_res, g_res);
    cudaGetSymbolAddress((void**)&p_tw, g_tw);
    cudaGetSymbolAddress((void**)&p_dinv, g_dinv);
    cudaGetSymbolAddress((void**)&p_outdeg, g_outdeg);
    cudaGetSymbolAddress((void**)&p_fus, g_fus);
    cudaGetSymbolAddress((void**)&p_nf, g_nf);
    cudaGetSymbolAddress((void**)&p_hid, g_hid);

    float* outp = (float*)d_out;

    // zero accumulators
    cudaMemsetAsync(p_dinv, 0, (size_t)N * sizeof(float));
    cudaMemsetAsync(p_outdeg, 0, (size_t)N * sizeof(int));
    cudaMemsetAsync(p_acc, 0, (size_t)N * 64 * sizeof(float));
    cudaMemsetAsync(p_fus, 0, (size_t)N * 192 * sizeof(float));

    // degrees
    k_deg<<<(E + 255) / 256, 256>>>(src, dst, p_dinv, p_outdeg, E);
    k_dinv<<<(N + 255) / 256, 256>>>(p_dinv, N);

    // time table
    k_ttable<<<1000, 64>>>(Temb, Wt, bt, p_tw);

    const int gemm_grid = (N + 255) / 256;

    // x_enc = relu(x @ Wn + bn)
    k_gemm_rows<128, true><<<gemm_grid, 256>>>(x, Wn, bn, nullptr, p_xenc, N);

    // conv1: h' = (x_enc @ Wc1) * dinv[row]
    k_gemm_rows<64, false><<<gemm_grid, 256>>>(p_xenc, Wc1, nullptr, p_dinv, p_h, N);
    k_conv_scatter<<<(E * 16 + 255) / 256, 256>>>(p_h, src, dst, p_acc, E);
    k_conv_fin<<<(N * 64 + 255) / 256, 256>>>(p_acc, p_h, p_dinv, bc1, nullptr, p_x1, N);

    // residual (x_enc @ Wr + br)
    k_gemm_rows<64, false><<<gemm_grid, 256>>>(p_xenc, Wr, br, nullptr, p_res, N);

    // conv2
    cudaMemsetAsync(p_acc, 0, (size_t)N * 64 * sizeof(float));
    k_gemm_rows<64, false><<<gemm_grid, 256>>>(p_x1, Wc2, nullptr, p_dinv, p_h, N);
    k_conv_scatter<<<(E * 16 + 255) / 256, 256>>>(p_h, src, dst, p_acc, E);
    k_conv_fin<<<(N * 64 + 255) / 256, 256>>>(p_acc, p_h, p_dinv, bc2, p_res, p_x2, N);

    // fusion scatter (edge_enc computed on the fly; time via table gather)
    k_fusion_scatter<<<(E + 7) / 8, 256>>>(p_x2, p_tw, eatt, We, be, src, dst, ts, p_fus, E);

    // node_fusion build + empty-node fallback
    k_fusion_fin<<<N, 64>>>(p_x2, p_xenc, p_fus, p_outdeg, p_nf, N);

    // classifier
    k_gemm_rows<256, true><<<gemm_grid, 256>>>(p_nf, Wm1, bm1, nullptr, p_hid, N);
    k_mlp_out<<<(N + 7) / 8, 256>>>(p_hid, Wm2, bm2, outp, N);
}

// round 4
// speedup vs baseline: 1.4476x; 1.1427x over previous
#include <cuda_runtime.h>
#include <cstdint>

#define MAXN 100000
#define MAXE 800000
#define H 64

// ---------------- device scratch ----------------
__device__ float g_xenc[MAXN * H];
__device__ float g_h[MAXN * H];
__device__ float g_acc[MAXN * H];
__device__ float g_x1[MAXN * H];
__device__ float g_x2[MAXN * H];
__device__ float g_res[MAXN * H];
__device__ float g_tw[1000 * H];
__device__ float g_dinv[MAXN];
__device__ int   g_outdeg[MAXN];
__device__ float g_fus[MAXN * 3 * H];
__device__ float g_nf[MAXN * 4 * H];
__device__ float g_hid[MAXN * H];

// ---------------- degree kernels ----------------
__global__ void k_deg(const int* __restrict__ src, const int* __restrict__ dst,
                      float* __restrict__ degf, int* __restrict__ outdeg, int E) {
    int i = blockIdx.x * blockDim.x + threadIdx.x;
    if (i < E) {
        atomicAdd(&degf[dst[i]], 1.0f);
        atomicAdd(&outdeg[src[i]], 1);
    }
}

__global__ void k_dinv(float* __restrict__ degf, int N) {
    int i = blockIdx.x * blockDim.x + threadIdx.x;
    if (i < N) degf[i] = rsqrtf(degf[i] + 1.0f);
}

// ---------------- time table ----------------
__global__ void k_ttable(const float* __restrict__ Temb, const float* __restrict__ Wt,
                         const float* __restrict__ bt, float* __restrict__ tw) {
    __shared__ float er[H];
    int t = blockIdx.x;
    int c = threadIdx.x;
    er[c] = Temb[t * H + c];
    __syncthreads();
    float a = bt[c];
#pragma unroll
    for (int k = 0; k < H; k++) a += er[k] * Wt[k * H + c];
    tw[t * H + c] = fmaxf(a, 0.0f);
}

// ---------------- tiled SGEMM: [M,K] @ [K,64] ----------------
// BM=128, BN=64, BK=16, 256 threads, 8x4 per-thread micro-tile.
// Per k-step per thread: 2 LDS.128 (A-frag) + 1 LDS.128 (B-frag) + 32 FFMA.
template <int K, bool RELU>
__global__ __launch_bounds__(256)
void k_gemm(const float* __restrict__ A, const float* __restrict__ W,
            const float* __restrict__ bias, const float* __restrict__ rowscale,
            float* __restrict__ C, int M) {
    __shared__ float As[16][132];   // transposed A tile, padded (16B-aligned rows)
    __shared__ float Bs[16][64];
    __shared__ float bsm[64];

    const int tid = threadIdx.x;
    const int tx = tid & 15;        // col group: cols tx*4 .. tx*4+3
    const int ty = tid >> 4;        // row group: rows ty*8 .. ty*8+7
    const int m0 = blockIdx.x * 128;

    if (tid < 64) bsm[tid] = bias ? bias[tid] : 0.0f;

    float acc[8][4];
#pragma unroll
    for (int i = 0; i < 8; i++)
#pragma unroll
        for (int j = 0; j < 4; j++) acc[i][j] = 0.0f;

    for (int kc = 0; kc < K; kc += 16) {
        __syncthreads();
        // load A tile 128x16 (512 float4), store transposed
#pragma unroll
        for (int f = tid; f < 512; f += 256) {
            int row = f >> 2, kq = f & 3;
            int gr = m0 + row;
            float4 v = make_float4(0.f, 0.f, 0.f, 0.f);
            if (gr < M) v = *(const float4*)(A + (size_t)gr * K + kc + kq * 4);
            As[kq * 4 + 0][row] = v.x;
            As[kq * 4 + 1][row] = v.y;
            As[kq * 4 + 2][row] = v.z;
            As[kq * 4 + 3][row] = v.w;
        }
        // load B tile 16x64 (256 float4)
        {
            int krow = tid >> 4, cq = tid & 15;
            *(float4*)&Bs[krow][cq * 4] = *(const float4*)(W + (size_t)(kc + krow) * 64 + cq * 4);
        }
        __syncthreads();
#pragma unroll
        for (int kk = 0; kk < 16; kk++) {
            float af[8], bf[4];
            *(float4*)&af[0] = *(const float4*)&As[kk][ty * 8];
            *(float4*)&af[4] = *(const float4*)&As[kk][ty * 8 + 4];
            *(float4*)&bf[0] = *(const float4*)&Bs[kk][tx * 4];
#pragma unroll
            for (int i = 0; i < 8; i++)
#pragma unroll
                for (int j = 0; j < 4; j++)
                    acc[i][j] = fmaf(af[i], bf[j], acc[i][j]);
        }
    }

#pragma unroll
    for (int i = 0; i < 8; i++) {
        int row = m0 + ty * 8 + i;
        if (row < M) {
            float sc = rowscale ? rowscale[row] : 1.0f;
            float4 v;
            v.x = acc[i][0] + bsm[tx * 4 + 0];
            v.y = acc[i][1] + bsm[tx * 4 + 1];
            v.z = acc[i][2] + bsm[tx * 4 + 2];
            v.w = acc[i][3] + bsm[tx * 4 + 3];
            if (RELU) {
                v.x = fmaxf(v.x, 0.f); v.y = fmaxf(v.y, 0.f);
                v.z = fmaxf(v.z, 0.f); v.w = fmaxf(v.w, 0.f);
            }
            v.x *= sc; v.y *= sc; v.z *= sc; v.w *= sc;
            *(float4*)(C + (size_t)row * 64 + tx * 4) = v;
        }
    }
}

// ---------------- GCN message scatter: acc[dst] += h'[src] ----------------
__global__ void k_conv_scatter(const float* __restrict__ h, const int* __restrict__ src,
                               const int* __restrict__ dst, float* __restrict__ acc, int E) {
    int u = blockIdx.x * blockDim.x + threadIdx.x;
    int total = E * 16;
    if (u >= total) return;
    int e = u >> 4, q = u & 15;
    float4 v = ((const float4*)h)[(size_t)src[e] * 16 + q];
    atomicAdd(((float4*)acc) + (size_t)dst[e] * 16 + q, v);
}

// ---------------- conv finalize ----------------
__global__ void k_conv_fin(const float* __restrict__ acc, const float* __restrict__ h,
                           const float* __restrict__ dinv, const float* __restrict__ bias,
                           const float* __restrict__ res, float* __restrict__ out, int N) {
    int i = blockIdx.x * blockDim.x + threadIdx.x;
    if (i >= N * 64) return;
    int n = i >> 6, c = i & 63;
    float v = (acc[i] + h[i]) * dinv[n] + bias[c];
    if (res) v += res[i];
    out[i] = fmaxf(v, 0.0f);
}

// ---------------- fusion scatter: warp per edge, float4 atomics via lane pairing --------
__global__ void k_fusion_scatter(const float* __restrict__ x2, const float* __restrict__ tw,
                                 const float* __restrict__ edge_attr,
                                 const float* __restrict__ We, const float* __restrict__ be,
                                 const int* __restrict__ src, const int* __restrict__ dst,
                                 const int* __restrict__ ts, float* __restrict__ fus, int E) {
    __shared__ float Ws[32 * 64];
    __shared__ float bes[64];
    int tid = threadIdx.x;
    for (int i = tid; i < 32 * 64; i += blockDim.x) Ws[i] = We[i];
    if (tid < 64) bes[tid] = be[tid];
    __syncthreads();

    int warp = (blockIdx.x * blockDim.x + tid) >> 5;
    int lane = tid & 31;
    if (warp >= E) return;
    int e = warp;
    int s = src[e], d = dst[e];
    int t = min(max(ts[e], 0), 999);

    float2 xd = *(const float2*)(x2 + (size_t)d * 64 + 2 * lane);
    float2 te = *(const float2*)(tw + (size_t)t * 64 + 2 * lane);
    float ea = edge_attr[(size_t)e * 32 + lane];

    float a0 = 0.0f, a1 = 0.0f;
#pragma unroll
    for (int k = 0; k < 32; k++) {
        float v = __shfl_sync(0xffffffffu, ea, k);
        float2 w = *(const float2*)&Ws[k * 64 + 2 * lane];
        a0 += v * w.x;
        a1 += v * w.y;
    }
    float2 ee;
    ee.x = fmaxf(a0 + bes[2 * lane], 0.0f);
    ee.y = fmaxf(a1 + bes[2 * lane + 1], 0.0f);

    // pair adjacent lanes' float2 -> float4 via shfl_xor; halves RED lane-ops
    float* base = fus + (size_t)s * 192;
    const unsigned FULL = 0xffffffffu;
    bool even = (lane & 1) == 0;

    float2 p;
    float4 v4;
    // block 0: x2[dst]
    p.x = __shfl_xor_sync(FULL, xd.x, 1);
    p.y = __shfl_xor_sync(FULL, xd.y, 1);
    if (even) { v4 = make_float4(xd.x, xd.y, p.x, p.y);
                atomicAdd((float4*)(base + 2 * lane), v4); }
    // block 1: edge_enc (odd lanes issue)
    p.x = __shfl_xor_sync(FULL, ee.x, 1);
    p.y = __shfl_xor_sync(FULL, ee.y, 1);
    if (!even) { v4 = make_float4(p.x, p.y, ee.x, ee.y);
                 atomicAdd((float4*)(base + 64 + 2 * (lane - 1)), v4); }
    // block 2: time_enc (even lanes issue)
    p.x = __shfl_xor_sync(FULL, te.x, 1);
    p.y = __shfl_xor_sync(FULL, te.y, 1);
    if (even) { v4 = make_float4(te.x, te.y, p.x, p.y);
                atomicAdd((float4*)(base + 128 + 2 * lane), v4); }
}

// ---------------- fusion finalize ----------------
__global__ void k_fusion_fin(const float* __restrict__ x2, const float* __restrict__ xenc,
                             const float* __restrict__ fus, const int* __restrict__ outdeg,
                             float* __restrict__ nf, int N) {
    __shared__ float sm[2];
    int n = blockIdx.x;
    int c = threadIdx.x;  // 64
    int od = outdeg[n];
    float* o = nf + (size_t)n * 256;
    if (od == 0) {
        float v = xenc[(size_t)n * 64 + c];
        o[c] = v; o[64 + c] = v; o[128 + c] = v; o[192 + c] = v;
        return;
    }
    float inv = 1.0f / (float)od;
    float f0 = x2[(size_t)n * 64 + c];
    const float* fb = fus + (size_t)n * 192;
    float f1 = fb[c] * inv;
    float f2 = fb[64 + c] * inv;
    float f3 = fb[128 + c] * inv;
    float s = fabsf(f0) + fabsf(f1) + fabsf(f2) + fabsf(f3);
#pragma unroll
    for (int off = 16; off > 0; off >>= 1) s += __shfl_xor_sync(0xffffffffu, s, off);
    if ((c & 31) == 0) sm[c >> 5] = s;
    __syncthreads();
    float total = sm[0] + sm[1];
    if (total < 1e-6f) {
        float v = xenc[(size_t)n * 64 + c];
        o[c] = v; o[64 + c] = v; o[128 + c] = v; o[192 + c] = v;
    } else {
        o[c] = f0; o[64 + c] = f1; o[128 + c] = f2; o[192 + c] = f3;
    }
}

// ---------------- MLP output ----------------
__global__ void k_mlp_out(const float* __restrict__ hid, const float* __restrict__ Wm2,
                          const float* __restrict__ bm2, float* __restrict__ out, int N) {
    int warp = (blockIdx.x * blockDim.x + threadIdx.x) >> 5;
    int lane = threadIdx.x & 31;
    if (warp >= N) return;
    int n = warp;
    float h0 = hid[(size_t)n * 64 + lane];
    float h1 = hid[(size_t)n * 64 + 32 + lane];
    float o0 = h0 * Wm2[lane * 2] + h1 * Wm2[(32 + lane) * 2];
    float o1 = h0 * Wm2[lane * 2 + 1] + h1 * Wm2[(32 + lane) * 2 + 1];
#pragma unroll
    for (int off = 16; off > 0; off >>= 1) {
        o0 += __shfl_xor_sync(0xffffffffu, o0, off);
        o1 += __shfl_xor_sync(0xffffffffu, o1, off);
    }
    if (lane == 0) {
        out[(size_t)n * 2]     = o0 + bm2[0];
        out[(size_t)n * 2 + 1] = o1 + bm2[1];
    }
}

// ---------------- host launcher ----------------
extern "C" void kernel_launch(void* const* d_in, const int* in_sizes, int n_in,
                              void* d_out, int out_size) {
    const float* x    = (const float*)d_in[0];
    const int*   ei   = (const int*)d_in[1];
    const float* eatt = (const float*)d_in[2];
    const int*   ts   = (const int*)d_in[3];
    const float* Wn   = (const float*)d_in[4];
    const float* bn   = (const float*)d_in[5];
    const float* We   = (const float*)d_in[6];
    const float* be   = (const float*)d_in[7];
    const float* Temb = (const float*)d_in[8];
    const float* Wt   = (const float*)d_in[9];
    const float* bt   = (const float*)d_in[10];
    const float* Wc1  = (const float*)d_in[11];
    const float* bc1  = (const float*)d_in[12];
    const float* Wc2  = (const float*)d_in[13];
    const float* bc2  = (const float*)d_in[14];
    const float* Wr   = (const float*)d_in[15];
    const float* br   = (const float*)d_in[16];
    const float* Wm1  = (const float*)d_in[17];
    const float* bm1  = (const float*)d_in[18];
    const float* Wm2  = (const float*)d_in[19];
    const float* bm2  = (const float*)d_in[20];

    const int N = in_sizes[0] / 128;
    const int E = in_sizes[3];
    const int* src = ei;
    const int* dst = ei + E;

    float *p_xenc, *p_h, *p_acc, *p_x1, *p_x2, *p_res, *p_tw, *p_dinv, *p_fus, *p_nf, *p_hid;
    int* p_outdeg;
    cudaGetSymbolAddress((void**)&p_xenc, g_xenc);
    cudaGetSymbolAddress((void**)&p_h, g_h);
    cudaGetSymbolAddress((void**)&p_acc, g_acc);
    cudaGetSymbolAddress((void**)&p_x1, g_x1);
    cudaGetSymbolAddress((void**)&p_x2, g_x2);
    cudaGetSymbolAddress((void**)&p_res, g_res);
    cudaGetSymbolAddress((void**)&p_tw, g_tw);
    cudaGetSymbolAddress((void**)&p_dinv, g_dinv);
    cudaGetSymbolAddress((void**)&p_outdeg, g_outdeg);
    cudaGetSymbolAddress((void**)&p_fus, g_fus);
    cudaGetSymbolAddress((void**)&p_nf, g_nf);
    cudaGetSymbolAddress((void**)&p_hid, g_hid);

    float* outp = (float*)d_out;

    cudaMemsetAsync(p_dinv, 0, (size_t)N * sizeof(float));
    cudaMemsetAsync(p_outdeg, 0, (size_t)N * sizeof(int));
    cudaMemsetAsync(p_acc, 0, (size_t)N * 64 * sizeof(float));
    cudaMemsetAsync(p_fus, 0, (size_t)N * 192 * sizeof(float));

    k_deg<<<(E + 255) / 256, 256>>>(src, dst, p_dinv, p_outdeg, E);
    k_dinv<<<(N + 255) / 256, 256>>>(p_dinv, N);

    k_ttable<<<1000, 64>>>(Temb, Wt, bt, p_tw);

    const int gg = (N + 127) / 128;

    // x_enc = relu(x @ Wn + bn)
    k_gemm<128, true><<<gg, 256>>>(x, Wn, bn, nullptr, p_xenc, N);

    // conv1: h' = (x_enc @ Wc1) * dinv[row]
    k_gemm<64, false><<<gg, 256>>>(p_xenc, Wc1, nullptr, p_dinv, p_h, N);
    k_conv_scatter<<<(E * 16 + 255) / 256, 256>>>(p_h, src, dst, p_acc, E);
    k_conv_fin<<<(N * 64 + 255) / 256, 256>>>(p_acc, p_h, p_dinv, bc1, nullptr, p_x1, N);

    // residual
    k_gemm<64, false><<<gg, 256>>>(p_xenc, Wr, br, nullptr, p_res, N);

    // conv2
    cudaMemsetAsync(p_acc, 0, (size_t)N * 64 * sizeof(float));
    k_gemm<64, false><<<gg, 256>>>(p_x1, Wc2, nullptr, p_dinv, p_h, N);
    k_conv_scatter<<<(E * 16 + 255) / 256, 256>>>(p_h, src, dst, p_acc, E);
    k_conv_fin<<<(N * 64 + 255) / 256, 256>>>(p_acc, p_h, p_dinv, bc2, p_res, p_x2, N);

    // fusion
    k_fusion_scatter<<<(E + 7) / 8, 256>>>(p_x2, p_tw, eatt, We, be, src, dst, ts, p_fus, E);
    k_fusion_fin<<<N, 64>>>(p_x2, p_xenc, p_fus, p_outdeg, p_nf, N);

    // classifier
    k_gemm<256, true><<<gg, 256>>>(p_nf, Wm1, bm1, nullptr, p_hid, N);
    k_mlp_out<<<(N + 7) / 8, 256>>>(p_hid, Wm2, bm2, outp, N);
}

// round 5
// speedup vs baseline: 1.5036x; 1.0387x over previous
#include <cuda_runtime.h>
#include <cstdint>

#define MAXN 100000
#define MAXE 800000
#define H 64
#define SCAN_PAD (MAXN + 2048)

// ---------------- device scratch ----------------
__device__ float g_xenc[MAXN * H];
__device__ float g_h[MAXN * H];
__device__ float g_x1[MAXN * H];
__device__ float g_x2[MAXN * H];
__device__ float g_res[MAXN * H];
__device__ float g_tw[1000 * H];
__device__ float g_dinv[MAXN];
__device__ float g_nf[MAXN * 4 * H];
__device__ float g_hid[MAXN * H];

__device__ int  g_indeg[MAXN];
__device__ int  g_outdeg[MAXN];
__device__ int  g_offD[SCAN_PAD];
__device__ int  g_offS[SCAN_PAD];
__device__ int  g_curD[MAXN];
__device__ int  g_curS[MAXN];
__device__ int  g_bsum[256];
__device__ int  g_srcD[MAXE];
__device__ int4 g_epk[MAXE];   // {e, dst, ts, 0} permuted by src

// ---------------- histogram ----------------
__global__ void k_hist(const int* __restrict__ src, const int* __restrict__ dst,
                       int* __restrict__ indeg, int* __restrict__ outdeg, int E) {
    int i = blockIdx.x * blockDim.x + threadIdx.x;
    if (i < E) {
        atomicAdd(&indeg[dst[i]], 1);
        atomicAdd(&outdeg[src[i]], 1);
    }
}

__global__ void k_dinv(const int* __restrict__ indeg, float* __restrict__ dinv, int N) {
    int i = blockIdx.x * blockDim.x + threadIdx.x;
    if (i < N) dinv[i] = rsqrtf((float)indeg[i] + 1.0f);
}

// ---------------- exclusive scan (3-kernel, 1024/block) ----------------
__global__ void k_scan_blk(const int* __restrict__ in, int* __restrict__ out,
                           int* __restrict__ bsum, int n) {
    __shared__ int sm[1024];
    int tid = threadIdx.x;
    int i = blockIdx.x * 1024 + tid;
    int v = (i < n) ? in[i] : 0;
    sm[tid] = v;
    __syncthreads();
#pragma unroll
    for (int off = 1; off < 1024; off <<= 1) {
        int t = (tid >= off) ? sm[tid - off] : 0;
        __syncthreads();
        sm[tid] += t;
        __syncthreads();
    }
    out[i] = sm[tid] - v;  // exclusive
    if (tid == 1023) bsum[blockIdx.x] = sm[1023];
}

__global__ void k_scan_top(int* __restrict__ bsum, int nb) {
    __shared__ int sm[256];
    int tid = threadIdx.x;
    int v = (tid < nb) ? bsum[tid] : 0;
    sm[tid] = v;
    __syncthreads();
#pragma unroll
    for (int off = 1; off < 256; off <<= 1) {
        int t = (tid >= off) ? sm[tid - off] : 0;
        __syncthreads();
        sm[tid] += t;
        __syncthreads();
    }
    if (tid < nb) bsum[tid] = sm[tid] - v;
}

__global__ void k_scan_add(int* __restrict__ out, const int* __restrict__ bsum) {
    out[blockIdx.x * 1024 + threadIdx.x] += bsum[blockIdx.x];
}

// ---------------- permute edges into CSR order ----------------
__global__ void k_scatter_ids(const int* __restrict__ src, const int* __restrict__ dst,
                              const int* __restrict__ ts,
                              int* __restrict__ curD, int* __restrict__ curS,
                              int* __restrict__ srcD, int4* __restrict__ epk, int E) {
    int e = blockIdx.x * blockDim.x + threadIdx.x;
    if (e >= E) return;
    int s = src[e], d = dst[e];
    int p = atomicAdd(&curD[d], 1);
    srcD[p] = s;
    int q = atomicAdd(&curS[s], 1);
    epk[q] = make_int4(e, d, min(max(ts[e], 0), 999), 0);
}

// ---------------- time table ----------------
__global__ void k_ttable(const float* __restrict__ Temb, const float* __restrict__ Wt,
                         const float* __restrict__ bt, float* __restrict__ tw) {
    __shared__ float er[H];
    int t = blockIdx.x;
    int c = threadIdx.x;
    er[c] = Temb[t * H + c];
    __syncthreads();
    float a = bt[c];
#pragma unroll
    for (int k = 0; k < H; k++) a += er[k] * Wt[k * H + c];
    tw[t * H + c] = fmaxf(a, 0.0f);
}

// ---------------- tiled SGEMM: [M,K] @ [K,64] ----------------
template <int K, bool RELU>
__global__ __launch_bounds__(256)
void k_gemm(const float* __restrict__ A, const float* __restrict__ W,
            const float* __restrict__ bias, const float* __restrict__ rowscale,
            float* __restrict__ C, int M) {
    __shared__ float As[16][132];
    __shared__ float Bs[16][64];
    __shared__ float bsm[64];

    const int tid = threadIdx.x;
    const int tx = tid & 15;
    const int ty = tid >> 4;
    const int m0 = blockIdx.x * 128;

    if (tid < 64) bsm[tid] = bias ? bias[tid] : 0.0f;

    float acc[8][4];
#pragma unroll
    for (int i = 0; i < 8; i++)
#pragma unroll
        for (int j = 0; j < 4; j++) acc[i][j] = 0.0f;

    for (int kc = 0; kc < K; kc += 16) {
        __syncthreads();
#pragma unroll
        for (int f = tid; f < 512; f += 256) {
            int row = f >> 2, kq = f & 3;
            int gr = m0 + row;
            float4 v = make_float4(0.f, 0.f, 0.f, 0.f);
            if (gr < M) v = *(const float4*)(A + (size_t)gr * K + kc + kq * 4);
            As[kq * 4 + 0][row] = v.x;
            As[kq * 4 + 1][row] = v.y;
            As[kq * 4 + 2][row] = v.z;
            As[kq * 4 + 3][row] = v.w;
        }
        {
            int krow = tid >> 4, cq = tid & 15;
            *(float4*)&Bs[krow][cq * 4] = *(const float4*)(W + (size_t)(kc + krow) * 64 + cq * 4);
        }
        __syncthreads();
#pragma unroll
        for (int kk = 0; kk < 16; kk++) {
            float af[8], bf[4];
            *(float4*)&af[0] = *(const float4*)&As[kk][ty * 8];
            *(float4*)&af[4] = *(const float4*)&As[kk][ty * 8 + 4];
            *(float4*)&bf[0] = *(const float4*)&Bs[kk][tx * 4];
#pragma unroll
            for (int i = 0; i < 8; i++)
#pragma unroll
                for (int j = 0; j < 4; j++)
                    acc[i][j] = fmaf(af[i], bf[j], acc[i][j]);
        }
    }

#pragma unroll
    for (int i = 0; i < 8; i++) {
        int row = m0 + ty * 8 + i;
        if (row < M) {
            float sc = rowscale ? rowscale[row] : 1.0f;
            float4 v;
            v.x = acc[i][0] + bsm[tx * 4 + 0];
            v.y = acc[i][1] + bsm[tx * 4 + 1];
            v.z = acc[i][2] + bsm[tx * 4 + 2];
            v.w = acc[i][3] + bsm[tx * 4 + 3];
            if (RELU) {
                v.x = fmaxf(v.x, 0.f); v.y = fmaxf(v.y, 0.f);
                v.z = fmaxf(v.z, 0.f); v.w = fmaxf(v.w, 0.f);
            }
            v.x *= sc; v.y *= sc; v.z *= sc; v.w *= sc;
            *(float4*)(C + (size_t)row * 64 + tx * 4) = v;
        }
    }
}

// ---------------- conv aggregate (CSR-by-dst gather, fused finalize) ----------------
// out[n] = relu((h'[n] + sum_{e: dst=n} h'[src_e]) * dinv[n] + bias [+ res])
__global__ __launch_bounds__(256)
void k_conv(const float* __restrict__ h, const float* __restrict__ dinv,
            const float* __restrict__ bias, const float* __restrict__ res,
            const int* __restrict__ offD, const int* __restrict__ srcD,
            float* __restrict__ out, int N) {
    int warp = (blockIdx.x * blockDim.x + threadIdx.x) >> 5;
    int lane = threadIdx.x & 31;
    if (warp >= N) return;
    int n = warp;
    int beg = offD[n], end = offD[n + 1];

    float2 a = *(const float2*)(h + (size_t)n * 64 + 2 * lane);  // self loop
    for (int j = beg; j < end; j++) {
        int s = srcD[j];
        float2 v = *(const float2*)(h + (size_t)s * 64 + 2 * lane);
        a.x += v.x;
        a.y += v.y;
    }
    float di = dinv[n];
    float2 b = *(const float2*)(bias + 2 * lane);
    float2 o;
    o.x = a.x * di + b.x;
    o.y = a.y * di + b.y;
    if (res) {
        float2 r = *(const float2*)(res + (size_t)n * 64 + 2 * lane);
        o.x += r.x;
        o.y += r.y;
    }
    o.x = fmaxf(o.x, 0.0f);
    o.y = fmaxf(o.y, 0.0f);
    *(float2*)(out + (size_t)n * 64 + 2 * lane) = o;
}

// ---------------- fusion aggregate (CSR-by-src gather, fused finalize) ----------------
// nf[n] = [ x2[n] | mean x2[dst] | mean relu(ea@We+be) | mean tw[ts] ]  with fallback
__global__ __launch_bounds__(256)
void k_fusion(const float* __restrict__ x2, const float* __restrict__ xenc,
              const float* __restrict__ tw, const float* __restrict__ eattr,
              const float* __restrict__ We, const float* __restrict__ be,
              const int* __restrict__ offS, const int4* __restrict__ epk,
              float* __restrict__ nf, int N) {
    int lane = threadIdx.x & 31;
    // Each lane owns output cols {2*lane, 2*lane+1}; keep its 2 We columns in regs.
    float2 w[32];
#pragma unroll
    for (int k = 0; k < 32; k++) w[k] = *(const float2*)(We + k * 64 + 2 * lane);
    float2 bee = *(const float2*)(be + 2 * lane);

    int warp = (blockIdx.x * blockDim.x + threadIdx.x) >> 5;
    if (warp >= N) return;
    int n = warp;
    int beg = offS[n], end = offS[n + 1];

    float* o = nf + (size_t)n * 256;
    float2 f0 = *(const float2*)(x2 + (size_t)n * 64 + 2 * lane);

    if (beg == end) {
        float2 xe = *(const float2*)(xenc + (size_t)n * 64 + 2 * lane);
        *(float2*)(o + 2 * lane) = xe;
        *(float2*)(o + 64 + 2 * lane) = xe;
        *(float2*)(o + 128 + 2 * lane) = xe;
        *(float2*)(o + 192 + 2 * lane) = xe;
        return;
    }

    float2 a0 = make_float2(0.f, 0.f), a1 = a0, a2 = a0;
    for (int j = beg; j < end; j++) {
        int4 ed = epk[j];
        float ea = eattr[(size_t)ed.x * 32 + lane];
        float2 xd = *(const float2*)(x2 + (size_t)ed.y * 64 + 2 * lane);
        float2 te = *(const float2*)(tw + (size_t)ed.z * 64 + 2 * lane);
        a0.x += xd.x; a0.y += xd.y;
        a2.x += te.x; a2.y += te.y;
        float m0 = bee.x, m1 = bee.y;
#pragma unroll
        for (int k = 0; k < 32; k++) {
            float v = __shfl_sync(0xffffffffu, ea, k);
            m0 = fmaf(v, w[k].x, m0);
            m1 = fmaf(v, w[k].y, m1);
        }
        a1.x += fmaxf(m0, 0.0f);
        a1.y += fmaxf(m1, 0.0f);
    }
    float inv = 1.0f / (float)(end - beg);
    float2 f1 = make_float2(a0.x * inv, a0.y * inv);
    float2 f2 = make_float2(a1.x * inv, a1.y * inv);
    float2 f3 = make_float2(a2.x * inv, a2.y * inv);

    float s = fabsf(f0.x) + fabsf(f0.y) + fabsf(f1.x) + fabsf(f1.y) +
              fabsf(f2.x) + fabsf(f2.y) + fabsf(f3.x) + fabsf(f3.y);
#pragma unroll
    for (int off = 16; off > 0; off >>= 1) s += __shfl_xor_sync(0xffffffffu, s, off);

    if (s < 1e-6f) {
        float2 xe = *(const float2*)(xenc + (size_t)n * 64 + 2 * lane);
        *(float2*)(o + 2 * lane) = xe;
        *(float2*)(o + 64 + 2 * lane) = xe;
        *(float2*)(o + 128 + 2 * lane) = xe;
        *(float2*)(o + 192 + 2 * lane) = xe;
    } else {
        *(float2*)(o + 2 * lane) = f0;
        *(float2*)(o + 64 + 2 * lane) = f1;
        *(float2*)(o + 128 + 2 * lane) = f2;
        *(float2*)(o + 192 + 2 * lane) = f3;
    }
}

// ---------------- MLP output ----------------
__global__ void k_mlp_out(const float* __restrict__ hid, const float* __restrict__ Wm2,
                          const float* __restrict__ bm2, float* __restrict__ out, int N) {
    int warp = (blockIdx.x * blockDim.x + threadIdx.x) >> 5;
    int lane = threadIdx.x & 31;
    if (warp >= N) return;
    int n = warp;
    float h0 = hid[(size_t)n * 64 + lane];
    float h1 = hid[(size_t)n * 64 + 32 + lane];
    float o0 = h0 * Wm2[lane * 2] + h1 * Wm2[(32 + lane) * 2];
    float o1 = h0 * Wm2[lane * 2 + 1] + h1 * Wm2[(32 + lane) * 2 + 1];
#pragma unroll
    for (int off = 16; off > 0; off >>= 1) {
        o0 += __shfl_xor_sync(0xffffffffu, o0, off);
        o1 += __shfl_xor_sync(0xffffffffu, o1, off);
    }
    if (lane == 0) {
        out[(size_t)n * 2]     = o0 + bm2[0];
        out[(size_t)n * 2 + 1] = o1 + bm2[1];
    }
}

// ---------------- host launcher ----------------
extern "C" void kernel_launch(void* const* d_in, const int* in_sizes, int n_in,
                              void* d_out, int out_size) {
    const float* x    = (const float*)d_in[0];
    const int*   ei   = (const int*)d_in[1];
    const float* eatt = (const float*)d_in[2];
    const int*   ts   = (const int*)d_in[3];
    const float* Wn   = (const float*)d_in[4];
    const float* bn   = (const float*)d_in[5];
    const float* We   = (const float*)d_in[6];
    const float* be   = (const float*)d_in[7];
    const float* Temb = (const float*)d_in[8];
    const float* Wt   = (const float*)d_in[9];
    const float* bt   = (const float*)d_in[10];
    const float* Wc1  = (const float*)d_in[11];
    const float* bc1  = (const float*)d_in[12];
    const float* Wc2  = (const float*)d_in[13];
    const float* bc2  = (const float*)d_in[14];
    const float* Wr   = (const float*)d_in[15];
    const float* br   = (const float*)d_in[16];
    const float* Wm1  = (const float*)d_in[17];
    const float* bm1  = (const float*)d_in[18];
    const float* Wm2  = (const float*)d_in[19];
    const float* bm2  = (const float*)d_in[20];

    const int N = in_sizes[0] / 128;
    const int E = in_sizes[3];
    const int* src = ei;
    const int* dst = ei + E;

    float *p_xenc, *p_h, *p_x1, *p_x2, *p_res, *p_tw, *p_dinv, *p_nf, *p_hid;
    int *p_indeg, *p_outdeg, *p_offD, *p_offS, *p_curD, *p_curS, *p_bsum, *p_srcD;
    int4* p_epk;
    cudaGetSymbolAddress((void**)&p_xenc, g_xenc);
    cudaGetSymbolAddress((void**)&p_h, g_h);
    cudaGetSymbolAddress((void**)&p_x1, g_x1);
    cudaGetSymbolAddress((void**)&p_x2, g_x2);
    cudaGetSymbolAddress((void**)&p_res, g_res);
    cudaGetSymbolAddress((void**)&p_tw, g_tw);
    cudaGetSymbolAddress((void**)&p_dinv, g_dinv);
    cudaGetSymbolAddress((void**)&p_nf, g_nf);
    cudaGetSymbolAddress((void**)&p_hid, g_hid);
    cudaGetSymbolAddress((void**)&p_indeg, g_indeg);
    cudaGetSymbolAddress((void**)&p_outdeg, g_outdeg);
    cudaGetSymbolAddress((void**)&p_offD, g_offD);
    cudaGetSymbolAddress((void**)&p_offS, g_offS);
    cudaGetSymbolAddress((void**)&p_curD, g_curD);
    cudaGetSymbolAddress((void**)&p_curS, g_curS);
    cudaGetSymbolAddress((void**)&p_bsum, g_bsum);
    cudaGetSymbolAddress((void**)&p_srcD, g_srcD);
    cudaGetSymbolAddress((void**)&p_epk, g_epk);

    float* outp = (float*)d_out;

    const int NB = (N + 1023) / 1024;  // scan blocks (<=98, padded arrays cover NB*1024)

    cudaMemsetAsync(p_indeg, 0, (size_t)N * sizeof(int));
    cudaMemsetAsync(p_outdeg, 0, (size_t)N * sizeof(int));

    // histogram + dinv
    k_hist<<<(E + 255) / 256, 256>>>(src, dst, p_indeg, p_outdeg, E);
    k_dinv<<<(N + 255) / 256, 256>>>(p_indeg, p_dinv, N);

    // CSR offsets: exclusive scans (padded, so offX[N] == E)
    k_scan_blk<<<NB, 1024>>>(p_indeg, p_offD, p_bsum, N);
    k_scan_top<<<1, 256>>>(p_bsum, NB);
    k_scan_add<<<NB, 1024>>>(p_offD, p_bsum);
    k_scan_blk<<<NB, 1024>>>(p_outdeg, p_offS, p_bsum, N);
    k_scan_top<<<1, 256>>>(p_bsum, NB);
    k_scan_add<<<NB, 1024>>>(p_offS, p_bsum);

    cudaMemcpyAsync(p_curD, p_offD, (size_t)N * sizeof(int), cudaMemcpyDeviceToDevice);
    cudaMemcpyAsync(p_curS, p_offS, (size_t)N * sizeof(int), cudaMemcpyDeviceToDevice);
    k_scatter_ids<<<(E + 255) / 256, 256>>>(src, dst, ts, p_curD, p_curS, p_srcD, p_epk, E);

    // time table
    k_ttable<<<1000, 64>>>(Temb, Wt, bt, p_tw);

    const int gg = (N + 127) / 128;
    const int wg = (N * 32 + 255) / 256;  // warp-per-node grids

    // x_enc = relu(x @ Wn + bn)
    k_gemm<128, true><<<gg, 256>>>(x, Wn, bn, nullptr, p_xenc, N);

    // conv1: h' = (x_enc @ Wc1) * dinv[row]; x1 = relu(gather + self)*dinv + b
    k_gemm<64, false><<<gg, 256>>>(p_xenc, Wc1, nullptr, p_dinv, p_h, N);
    k_conv<<<wg, 256>>>(p_h, p_dinv, bc1, nullptr, p_offD, p_srcD, p_x1, N);

    // residual
    k_gemm<64, false><<<gg, 256>>>(p_xenc, Wr, br, nullptr, p_res, N);

    // conv2 (+res)
    k_gemm<64, false><<<gg, 256>>>(p_x1, Wc2, nullptr, p_dinv, p_h, N);
    k_conv<<<wg, 256>>>(p_h, p_dinv, bc2, p_res, p_offD, p_srcD, p_x2, N);

    // fusion gather (edge matvec inline, We in registers)
    k_fusion<<<wg, 256>>>(p_x2, p_xenc, p_tw, eatt, We, be, p_offS, p_epk, p_nf, N);

    // classifier
    k_gemm<256, true><<<gg, 256>>>(p_nf, Wm1, bm1, nullptr, p_hid, N);
    k_mlp_out<<<(N + 7) / 8, 256>>>(p_hid, Wm2, bm2, outp, N);
}

// round 6
// speedup vs baseline: 1.7177x; 1.1424x over previous
#include <cuda_runtime.h>
#include <cstdint>

#define MAXN 100000
#define MAXE 800000
#define H 64
#define SCAN_PAD (MAXN + 2048)

// ---------------- device scratch ----------------
__device__ float g_xenc[MAXN * H];
__device__ float g_h[MAXN * H];
__device__ float g_x1[MAXN * H];
__device__ float g_x2[MAXN * H];
__device__ float g_res[MAXN * H];
__device__ float g_tw[1000 * H];
__device__ float g_dinv[MAXN];
__device__ float g_nf[MAXN * 4 * H];

__device__ int  g_indeg[MAXN];
__device__ int  g_outdeg[MAXN];
__device__ int  g_offD[SCAN_PAD];
__device__ int  g_offS[SCAN_PAD];
__device__ int  g_curD[MAXN];
__device__ int  g_curS[MAXN];
__device__ int  g_bsum[256];
__device__ int  g_srcD[MAXE];
__device__ int4 g_epk[MAXE];   // {e, dst, ts, 0} permuted by src

// ---------------- histogram ----------------
__global__ void k_hist(const int* __restrict__ src, const int* __restrict__ dst,
                       int* __restrict__ indeg, int* __restrict__ outdeg, int E) {
    int i = blockIdx.x * blockDim.x + threadIdx.x;
    if (i < E) {
        atomicAdd(&indeg[dst[i]], 1);
        atomicAdd(&outdeg[src[i]], 1);
    }
}

// ---------------- exclusive scan, two arrays at once (gridDim.y=2) ----------------
__global__ void k_scan_blk(const int* __restrict__ indeg, const int* __restrict__ outdeg,
                           int* __restrict__ offD, int* __restrict__ offS,
                           float* __restrict__ dinv, int* __restrict__ bsum, int n) {
    __shared__ int sm[1024];
    int y = blockIdx.y;
    const int* in = y ? outdeg : indeg;
    int* out = y ? offS : offD;
    int tid = threadIdx.x;
    int i = blockIdx.x * 1024 + tid;
    int v = (i < n) ? in[i] : 0;
    if (y == 0 && i < n) dinv[i] = rsqrtf((float)v + 1.0f);
    sm[tid] = v;
    __syncthreads();
#pragma unroll
    for (int off = 1; off < 1024; off <<= 1) {
        int t = (tid >= off) ? sm[tid - off] : 0;
        __syncthreads();
        sm[tid] += t;
        __syncthreads();
    }
    out[i] = sm[tid] - v;  // exclusive
    if (tid == 1023) bsum[y * 128 + blockIdx.x] = sm[1023];
}

__global__ void k_scan_top(int* __restrict__ bsum, int nb) {
    __shared__ int sm[128];
    int y = blockIdx.y;
    int tid = threadIdx.x;
    int v = (tid < nb) ? bsum[y * 128 + tid] : 0;
    sm[tid] = v;
    __syncthreads();
#pragma unroll
    for (int off = 1; off < 128; off <<= 1) {
        int t = (tid >= off) ? sm[tid - off] : 0;
        __syncthreads();
        sm[tid] += t;
        __syncthreads();
    }
    if (tid < nb) bsum[y * 128 + tid] = sm[tid] - v;
}

__global__ void k_scan_add(int* __restrict__ offD, int* __restrict__ offS,
                           int* __restrict__ curD, int* __restrict__ curS,
                           const int* __restrict__ bsum, int n) {
    int y = blockIdx.y;
    int* out = y ? offS : offD;
    int* cur = y ? curS : curD;
    int i = blockIdx.x * 1024 + threadIdx.x;
    int v = out[i] + bsum[y * 128 + blockIdx.x];
    out[i] = v;
    if (i < n) cur[i] = v;
}

// ---------------- permute edges into CSR order ----------------
__global__ void k_scatter_ids(const int* __restrict__ src, const int* __restrict__ dst,
                              const int* __restrict__ ts,
                              int* __restrict__ curD, int* __restrict__ curS,
                              int* __restrict__ srcD, int4* __restrict__ epk, int E) {
    int e = blockIdx.x * blockDim.x + threadIdx.x;
    if (e >= E) return;
    int s = src[e], d = dst[e];
    int p = atomicAdd(&curD[d], 1);
    srcD[p] = s;
    int q = atomicAdd(&curS[s], 1);
    epk[q] = make_int4(e, d, min(max(ts[e], 0), 999), 0);
}

// ---------------- time table ----------------
__global__ void k_ttable(const float* __restrict__ Temb, const float* __restrict__ Wt,
                         const float* __restrict__ bt, float* __restrict__ tw) {
    __shared__ float er[H];
    int t = blockIdx.x;
    int c = threadIdx.x;
    er[c] = Temb[t * H + c];
    __syncthreads();
    float a = bt[c];
#pragma unroll
    for (int k = 0; k < H; k++) a += er[k] * Wt[k * H + c];
    tw[t * H + c] = fmaxf(a, 0.0f);
}

// ---------------- tiled SGEMM: [M,K] @ [K,64] ----------------
template <int K, bool RELU>
__global__ __launch_bounds__(256)
void k_gemm(const float* __restrict__ A, const float* __restrict__ W,
            const float* __restrict__ bias, const float* __restrict__ rowscale,
            float* __restrict__ C, int M) {
    __shared__ float As[16][132];
    __shared__ float Bs[16][64];
    __shared__ float bsm[64];

    const int tid = threadIdx.x;
    const int tx = tid & 15;
    const int ty = tid >> 4;
    const int m0 = blockIdx.x * 128;

    if (tid < 64) bsm[tid] = bias ? bias[tid] : 0.0f;

    float acc[8][4];
#pragma unroll
    for (int i = 0; i < 8; i++)
#pragma unroll
        for (int j = 0; j < 4; j++) acc[i][j] = 0.0f;

    for (int kc = 0; kc < K; kc += 16) {
        __syncthreads();
#pragma unroll
        for (int f = tid; f < 512; f += 256) {
            int row = f >> 2, kq = f & 3;
            int gr = m0 + row;
            float4 v = make_float4(0.f, 0.f, 0.f, 0.f);
            if (gr < M) v = *(const float4*)(A + (size_t)gr * K + kc + kq * 4);
            As[kq * 4 + 0][row] = v.x;
            As[kq * 4 + 1][row] = v.y;
            As[kq * 4 + 2][row] = v.z;
            As[kq * 4 + 3][row] = v.w;
        }
        {
            int krow = tid >> 4, cq = tid & 15;
            *(float4*)&Bs[krow][cq * 4] = *(const float4*)(W + (size_t)(kc + krow) * 64 + cq * 4);
        }
        __syncthreads();
#pragma unroll
        for (int kk = 0; kk < 16; kk++) {
            float af[8], bf[4];
            *(float4*)&af[0] = *(const float4*)&As[kk][ty * 8];
            *(float4*)&af[4] = *(const float4*)&As[kk][ty * 8 + 4];
            *(float4*)&bf[0] = *(const float4*)&Bs[kk][tx * 4];
#pragma unroll
            for (int i = 0; i < 8; i++)
#pragma unroll
                for (int j = 0; j < 4; j++)
                    acc[i][j] = fmaf(af[i], bf[j], acc[i][j]);
        }
    }

#pragma unroll
    for (int i = 0; i < 8; i++) {
        int row = m0 + ty * 8 + i;
        if (row < M) {
            float sc = rowscale ? rowscale[row] : 1.0f;
            float4 v;
            v.x = acc[i][0] + bsm[tx * 4 + 0];
            v.y = acc[i][1] + bsm[tx * 4 + 1];
            v.z = acc[i][2] + bsm[tx * 4 + 2];
            v.w = acc[i][3] + bsm[tx * 4 + 3];
            if (RELU) {
                v.x = fmaxf(v.x, 0.f); v.y = fmaxf(v.y, 0.f);
                v.z = fmaxf(v.z, 0.f); v.w = fmaxf(v.w, 0.f);
            }
            v.x *= sc; v.y *= sc; v.z *= sc; v.w *= sc;
            *(float4*)(C + (size_t)row * 64 + tx * 4) = v;
        }
    }
}

// ---------------- dual SGEMM: H = (A@W1)*dinv[row], R = A@W2 + b2  (K=64) --------
__global__ __launch_bounds__(256)
void k_gemm_dual(const float* __restrict__ A, const float* __restrict__ W1,
                 const float* __restrict__ W2, const float* __restrict__ b2,
                 const float* __restrict__ dinv, float* __restrict__ Hh,
                 float* __restrict__ R, int M) {
    __shared__ float As[16][132];
    __shared__ float Bs[16][128];
    __shared__ float bsm[64];

    const int tid = threadIdx.x;
    const int tx = tid & 15;
    const int ty = tid >> 4;
    const int m0 = blockIdx.x * 128;

    if (tid < 64) bsm[tid] = b2[tid];

    float acc[8][8];
#pragma unroll
    for (int i = 0; i < 8; i++)
#pragma unroll
        for (int j = 0; j < 8; j++) acc[i][j] = 0.0f;

    for (int kc = 0; kc < 64; kc += 16) {
        __syncthreads();
#pragma unroll
        for (int f = tid; f < 512; f += 256) {
            int row = f >> 2, kq = f & 3;
            int gr = m0 + row;
            float4 v = make_float4(0.f, 0.f, 0.f, 0.f);
            if (gr < M) v = *(const float4*)(A + (size_t)gr * 64 + kc + kq * 4);
            As[kq * 4 + 0][row] = v.x;
            As[kq * 4 + 1][row] = v.y;
            As[kq * 4 + 2][row] = v.z;
            As[kq * 4 + 3][row] = v.w;
        }
#pragma unroll
        for (int f = tid; f < 512; f += 256) {
            int krow = f >> 5, cq = f & 31;
            float4 v = (cq < 16)
                ? *(const float4*)(W1 + (size_t)(kc + krow) * 64 + cq * 4)
                : *(const float4*)(W2 + (size_t)(kc + krow) * 64 + (cq - 16) * 4);
            *(float4*)&Bs[krow][cq * 4] = v;
        }
        __syncthreads();
#pragma unroll
        for (int kk = 0; kk < 16; kk++) {
            float af[8], bf[8];
            *(float4*)&af[0] = *(const float4*)&As[kk][ty * 8];
            *(float4*)&af[4] = *(const float4*)&As[kk][ty * 8 + 4];
            *(float4*)&bf[0] = *(const float4*)&Bs[kk][tx * 8];
            *(float4*)&bf[4] = *(const float4*)&Bs[kk][tx * 8 + 4];
#pragma unroll
            for (int i = 0; i < 8; i++)
#pragma unroll
                for (int j = 0; j < 8; j++)
                    acc[i][j] = fmaf(af[i], bf[j], acc[i][j]);
        }
    }

    const bool second = (tx >= 8);
    const int c0 = second ? (tx - 8) * 8 : tx * 8;
#pragma unroll
    for (int i = 0; i < 8; i++) {
        int row = m0 + ty * 8 + i;
        if (row < M) {
            if (!second) {
                float sc = dinv[row];
                float4 v0, v1;
                v0.x = acc[i][0] * sc; v0.y = acc[i][1] * sc;
                v0.z = acc[i][2] * sc; v0.w = acc[i][3] * sc;
                v1.x = acc[i][4] * sc; v1.y = acc[i][5] * sc;
                v1.z = acc[i][6] * sc; v1.w = acc[i][7] * sc;
                *(float4*)(Hh + (size_t)row * 64 + c0) = v0;
                *(float4*)(Hh + (size_t)row * 64 + c0 + 4) = v1;
            } else {
                float4 v0, v1;
                v0.x = acc[i][0] + bsm[c0 + 0]; v0.y = acc[i][1] + bsm[c0 + 1];
                v0.z = acc[i][2] + bsm[c0 + 2]; v0.w = acc[i][3] + bsm[c0 + 3];
                v1.x = acc[i][4] + bsm[c0 + 4]; v1.y = acc[i][5] + bsm[c0 + 5];
                v1.z = acc[i][6] + bsm[c0 + 6]; v1.w = acc[i][7] + bsm[c0 + 7];
                *(float4*)(R + (size_t)row * 64 + c0) = v0;
                *(float4*)(R + (size_t)row * 64 + c0 + 4) = v1;
            }
        }
    }
}

// ---------------- classifier: hid=relu(A@Wm1+bm1) in smem, out=hid@Wm2+bm2 ------
__global__ __launch_bounds__(256)
void k_gemm_cls(const float* __restrict__ A, const float* __restrict__ W,
                const float* __restrict__ bias, const float* __restrict__ Wm2,
                const float* __restrict__ bm2, float* __restrict__ out, int M) {
    __shared__ __align__(16) float pool[128 * 68];      // 34816 B (tile phase)
    float (*As)[132] = (float(*)[132])pool;             // 2112 floats
    float (*Bs)[64]  = (float(*)[64])(pool + 2112);     // 1024 floats
    __shared__ float bsm[64];
    __shared__ float wm2s[128];
    __shared__ float bm2s[2];

    const int tid = threadIdx.x;
    const int tx = tid & 15;
    const int ty = tid >> 4;
    const int m0 = blockIdx.x * 128;

    if (tid < 64) bsm[tid] = bias[tid];
    if (tid < 128) wm2s[tid] = Wm2[tid];
    if (tid < 2) bm2s[tid] = bm2[tid];

    float acc[8][4];
#pragma unroll
    for (int i = 0; i < 8; i++)
#pragma unroll
        for (int j = 0; j < 4; j++) acc[i][j] = 0.0f;

    for (int kc = 0; kc < 256; kc += 16) {
        __syncthreads();
#pragma unroll
        for (int f = tid; f < 512; f += 256) {
            int row = f >> 2, kq = f & 3;
            int gr = m0 + row;
            float4 v = make_float4(0.f, 0.f, 0.f, 0.f);
            if (gr < M) v = *(const float4*)(A + (size_t)gr * 256 + kc + kq * 4);
            As[kq * 4 + 0][row] = v.x;
            As[kq * 4 + 1][row] = v.y;
            As[kq * 4 + 2][row] = v.z;
            As[kq * 4 + 3][row] = v.w;
        }
        {
            int krow = tid >> 4, cq = tid & 15;
            *(float4*)&Bs[krow][cq * 4] = *(const float4*)(W + (size_t)(kc + krow) * 64 + cq * 4);
        }
        __syncthreads();
#pragma unroll
        for (int kk = 0; kk < 16; kk++) {
            float af[8], bf[4];
            *(float4*)&af[0] = *(const float4*)&As[kk][ty * 8];
            *(float4*)&af[4] = *(const float4*)&As[kk][ty * 8 + 4];
            *(float4*)&bf[0] = *(const float4*)&Bs[kk][tx * 4];
#pragma unroll
            for (int i = 0; i < 8; i++)
#pragma unroll
                for (int j = 0; j < 4; j++)
                    acc[i][j] = fmaf(af[i], bf[j], acc[i][j]);
        }
    }

    // write relu(hid) tile into smem (overwrites As/Bs)
    __syncthreads();
#pragma unroll
    for (int i = 0; i < 8; i++) {
        int lr = ty * 8 + i;
        float4 v;
        v.x = fmaxf(acc[i][0] + bsm[tx * 4 + 0], 0.f);
        v.y = fmaxf(acc[i][1] + bsm[tx * 4 + 1], 0.f);
        v.z = fmaxf(acc[i][2] + bsm[tx * 4 + 2], 0.f);
        v.w = fmaxf(acc[i][3] + bsm[tx * 4 + 3], 0.f);
        *(float4*)&pool[lr * 68 + tx * 4] = v;
    }
    __syncthreads();

    // out[row] = hid_row @ Wm2 + bm2 : thread t -> row t>>1, col t&1
    int r = tid >> 1, c = tid & 1;
    int row = m0 + r;
    if (row < M) {
        const float* hr = &pool[r * 68];
        float s = 0.0f;
#pragma unroll
        for (int k = 0; k < 64; k++) s = fmaf(hr[k], wm2s[k * 2 + c], s);
        out[(size_t)row * 2 + c] = s + bm2s[c];
    }
}

// ---------------- conv aggregate (CSR-by-dst gather, fused finalize) ----------------
__global__ __launch_bounds__(256)
void k_conv(const float* __restrict__ h, const float* __restrict__ dinv,
            const float* __restrict__ bias, const float* __restrict__ res,
            const int* __restrict__ offD, const int* __restrict__ srcD,
            float* __restrict__ out, int N) {
    int warp = (blockIdx.x * blockDim.x + threadIdx.x) >> 5;
    int lane = threadIdx.x & 31;
    if (warp >= N) return;
    int n = warp;
    int beg = offD[n], end = offD[n + 1];
    int cnt = end - beg;
    const unsigned FULL = 0xffffffffu;

    float2 a = *(const float2*)(h + (size_t)n * 64 + 2 * lane);  // self loop
    for (int base = 0; base < cnt; base += 32) {
        int idx = beg + base + lane;
        int sv = srcD[idx < end ? idx : (end - 1)];
        int m = min(32, cnt - base);
        for (int j = 0; j < m; j++) {
            int s = __shfl_sync(FULL, sv, j);
            float2 v = *(const float2*)(h + (size_t)s * 64 + 2 * lane);
            a.x += v.x;
            a.y += v.y;
        }
    }
    float di = dinv[n];
    float2 b = *(const float2*)(bias + 2 * lane);
    float2 o;
    o.x = a.x * di + b.x;
    o.y = a.y * di + b.y;
    if (res) {
        float2 r = *(const float2*)(res + (size_t)n * 64 + 2 * lane);
        o.x += r.x;
        o.y += r.y;
    }
    o.x = fmaxf(o.x, 0.0f);
    o.y = fmaxf(o.y, 0.0f);
    *(float2*)(out + (size_t)n * 64 + 2 * lane) = o;
}

// ---------------- fusion aggregate (CSR-by-src, pipelined gather) ----------------
__global__ __launch_bounds__(256)
void k_fusion(const float* __restrict__ x2, const float* __restrict__ xenc,
              const float* __restrict__ tw, const float* __restrict__ eattr,
              const float* __restrict__ We, const float* __restrict__ be,
              const int* __restrict__ offS, const int4* __restrict__ epk,
              float* __restrict__ nf, int N) {
    int lane = threadIdx.x & 31;
    float2 w[32];
#pragma unroll
    for (int k = 0; k < 32; k++) w[k] = *(const float2*)(We + k * 64 + 2 * lane);
    float2 bee = *(const float2*)(be + 2 * lane);

    int warp = (blockIdx.x * blockDim.x + threadIdx.x) >> 5;
    if (warp >= N) return;
    int n = warp;
    int beg = offS[n], end = offS[n + 1];
    int cnt = end - beg;
    const unsigned FULL = 0xffffffffu;

    float* o = nf + (size_t)n * 256;
    float2 f0 = *(const float2*)(x2 + (size_t)n * 64 + 2 * lane);

    if (cnt == 0) {
        float2 xe = *(const float2*)(xenc + (size_t)n * 64 + 2 * lane);
        *(float2*)(o + 2 * lane) = xe;
        *(float2*)(o + 64 + 2 * lane) = xe;
        *(float2*)(o + 128 + 2 * lane) = xe;
        *(float2*)(o + 192 + 2 * lane) = xe;
        return;
    }

    // chunk of edge records in lane regs; 2-deep pipeline over edges
    int idx0 = beg + lane;
    int4 my = epk[idx0 < end ? idx0 : (end - 1)];
    int e = __shfl_sync(FULL, my.x, 0);
    int d = __shfl_sync(FULL, my.y, 0);
    int t = __shfl_sync(FULL, my.z, 0);
    float  ean = eattr[(size_t)e * 32 + lane];
    float2 xdn = *(const float2*)(x2 + (size_t)d * 64 + 2 * lane);
    float2 ten = *(const float2*)(tw + (size_t)t * 64 + 2 * lane);

    float2 a0 = make_float2(0.f, 0.f), a1 = a0, a2 = a0;
    for (int j = 0; j < cnt; j++) {
        float ea = ean;
        float2 xd = xdn, te = ten;
        int jn = j + 1;
        if (jn < cnt) {
            int jj = jn & 31;
            if (jj == 0) {
                int idx = beg + jn + lane;
                my = epk[idx < end ? idx : (end - 1)];
            }
            e = __shfl_sync(FULL, my.x, jj);
            d = __shfl_sync(FULL, my.y, jj);
            t = __shfl_sync(FULL, my.z, jj);
            ean = eattr[(size_t)e * 32 + lane];
            xdn = *(const float2*)(x2 + (size_t)d * 64 + 2 * lane);
            ten = *(const float2*)(tw + (size_t)t * 64 + 2 * lane);
        }
        a0.x += xd.x; a0.y += xd.y;
        a2.x += te.x; a2.y += te.y;
        float m0 = bee.x, m1 = bee.y;
#pragma unroll
        for (int k = 0; k < 32; k++) {
            float v = __shfl_sync(FULL, ea, k);
            m0 = fmaf(v, w[k].x, m0);
            m1 = fmaf(v, w[k].y, m1);
        }
        a1.x += fmaxf(m0, 0.0f);
        a1.y += fmaxf(m1, 0.0f);
    }
    float inv = 1.0f / (float)cnt;
    float2 f1 = make_float2(a0.x * inv, a0.y * inv);
    float2 f2 = make_float2(a1.x * inv, a1.y * inv);
    float2 f3 = make_float2(a2.x * inv, a2.y * inv);

    float s = fabsf(f0.x) + fabsf(f0.y) + fabsf(f1.x) + fabsf(f1.y) +
              fabsf(f2.x) + fabsf(f2.y) + fabsf(f3.x) + fabsf(f3.y);
#pragma unroll
    for (int off = 16; off > 0; off >>= 1) s += __shfl_xor_sync(FULL, s, off);

    if (s < 1e-6f) {
        float2 xe = *(const float2*)(xenc + (size_t)n * 64 + 2 * lane);
        *(float2*)(o + 2 * lane) = xe;
        *(float2*)(o + 64 + 2 * lane) = xe;
        *(float2*)(o + 128 + 2 * lane) = xe;
        *(float2*)(o + 192 + 2 * lane) = xe;
    } else {
        *(float2*)(o + 2 * lane) = f0;
        *(float2*)(o + 64 + 2 * lane) = f1;
        *(float2*)(o + 128 + 2 * lane) = f2;
        *(float2*)(o + 192 + 2 * lane) = f3;
    }
}

// ---------------- host launcher ----------------
extern "C" void kernel_launch(void* const* d_in, const int* in_sizes, int n_in,
                              void* d_out, int out_size) {
    const float* x    = (const float*)d_in[0];
    const int*   ei   = (const int*)d_in[1];
    const float* eatt = (const float*)d_in[2];
    const int*   ts   = (const int*)d_in[3];
    const float* Wn   = (const float*)d_in[4];
    const float* bn   = (const float*)d_in[5];
    const float* We   = (const float*)d_in[6];
    const float* be   = (const float*)d_in[7];
    const float* Temb = (const float*)d_in[8];
    const float* Wt   = (const float*)d_in[9];
    const float* bt   = (const float*)d_in[10];
    const float* Wc1  = (const float*)d_in[11];
    const float* bc1  = (const float*)d_in[12];
    const float* Wc2  = (const float*)d_in[13];
    const float* bc2  = (const float*)d_in[14];
    const float* Wr   = (const float*)d_in[15];
    const float* br   = (const float*)d_in[16];
    const float* Wm1  = (const float*)d_in[17];
    const float* bm1  = (const float*)d_in[18];
    const float* Wm2  = (const float*)d_in[19];
    const float* bm2  = (const float*)d_in[20];

    const int N = in_sizes[0] / 128;
    const int E = in_sizes[3];
    const int* src = ei;
    const int* dst = ei + E;

    float *p_xenc, *p_h, *p_x1, *p_x2, *p_res, *p_tw, *p_dinv, *p_nf;
    int *p_indeg, *p_outdeg, *p_offD, *p_offS, *p_curD, *p_curS, *p_bsum, *p_srcD;
    int4* p_epk;
    cudaGetSymbolAddress((void**)&p_xenc, g_xenc);
    cudaGetSymbolAddress((void**)&p_h, g_h);
    cudaGetSymbolAddress((void**)&p_x1, g_x1);
    cudaGetSymbolAddress((void**)&p_x2, g_x2);
    cudaGetSymbolAddress((void**)&p_res, g_res);
    cudaGetSymbolAddress((void**)&p_tw, g_tw);
    cudaGetSymbolAddress((void**)&p_dinv, g_dinv);
    cudaGetSymbolAddress((void**)&p_nf, g_nf);
    cudaGetSymbolAddress((void**)&p_indeg, g_indeg);
    cudaGetSymbolAddress((void**)&p_outdeg, g_outdeg);
    cudaGetSymbolAddress((void**)&p_offD, g_offD);
    cudaGetSymbolAddress((void**)&p_offS, g_offS);
    cudaGetSymbolAddress((void**)&p_curD, g_curD);
    cudaGetSymbolAddress((void**)&p_curS, g_curS);
    cudaGetSymbolAddress((void**)&p_bsum, g_bsum);
    cudaGetSymbolAddress((void**)&p_srcD, g_srcD);
    cudaGetSymbolAddress((void**)&p_epk, g_epk);

    float* outp = (float*)d_out;

    const int NB = (N + 1023) / 1024;  // <=98

    cudaMemsetAsync(p_indeg, 0, (size_t)N * sizeof(int));
    cudaMemsetAsync(p_outdeg, 0, (size_t)N * sizeof(int));

    k_hist<<<(E + 255) / 256, 256>>>(src, dst, p_indeg, p_outdeg, E);

    k_scan_blk<<<dim3(NB, 2), 1024>>>(p_indeg, p_outdeg, p_offD, p_offS, p_dinv, p_bsum, N);
    k_scan_top<<<dim3(1, 2), 128>>>(p_bsum, NB);
    k_scan_add<<<dim3(NB, 2), 1024>>>(p_offD, p_offS, p_curD, p_curS, p_bsum, N);

    k_scatter_ids<<<(E + 255) / 256, 256>>>(src, dst, ts, p_curD, p_curS, p_srcD, p_epk, E);

    k_ttable<<<1000, 64>>>(Temb, Wt, bt, p_tw);

    const int gg = (N + 127) / 128;
    const int wg = (N * 32 + 255) / 256;

    // x_enc = relu(x @ Wn + bn)
    k_gemm<128, true><<<gg, 256>>>(x, Wn, bn, nullptr, p_xenc, N);

    // conv1 h' + residual in one pass over x_enc
    k_gemm_dual<<<gg, 256>>>(p_xenc, Wc1, Wr, br, p_dinv, p_h, p_res, N);
    k_conv<<<wg, 256>>>(p_h, p_dinv, bc1, nullptr, p_offD, p_srcD, p_x1, N);

    // conv2 (+res)
    k_gemm<64, false><<<gg, 256>>>(p_x1, Wc2, nullptr, p_dinv, p_h, N);
    k_conv<<<wg, 256>>>(p_h, p_dinv, bc2, p_res, p_offD, p_srcD, p_x2, N);

    // fusion gather (edge matvec inline, We in registers, pipelined loads)
    k_fusion<<<wg, 256>>>(p_x2, p_xenc, p_tw, eatt, We, be, p_offS, p_epk, p_nf, N);

    // classifier fused with final 64->2 projection
    k_gemm_cls<<<gg, 256>>>(p_nf, Wm1, bm1, Wm2, bm2, outp, N);
}